// round 2
// baseline (speedup 1.0000x reference)
#include <cuda_runtime.h>

#define NN 100000
#define NE 1600000
#define FD 128
#define NC 40
#define SCAN_BLK 1024
#define NSCAN ((NN + SCAN_BLK - 1) / SCAN_BLK)   // 98
#define LN_EPS 1e-5f

// ---------------- scratch (static device arrays; no allocation) ----------------
__device__ int   g_count[NN];
__device__ int   g_rowptr[NN + 1];
__device__ int   g_cursor[NN];
__device__ float g_dinv[NN];
__device__ int   g_csr_src[NE];
__device__ float g_csr_w[NE];
__device__ float g_hA[(size_t)NN * FD];
__device__ float g_hB[(size_t)NN * FD];
__device__ float g_h3[(size_t)NN * NC];
__device__ int   g_bsum[NSCAN];
__device__ int   g_boff[NSCAN];

// ---------------- CSR build ----------------
__global__ void k_init_count() {
    int i = blockIdx.x * blockDim.x + threadIdx.x;
    if (i < NN) g_count[i] = 0;
}

__global__ void k_hist(const int* __restrict__ dst) {
    int e = blockIdx.x * blockDim.x + threadIdx.x;
    if (e < NE) atomicAdd(&g_count[dst[e]], 1);
}

__global__ void k_dinv() {
    int i = blockIdx.x * blockDim.x + threadIdx.x;
    if (i < NN) g_dinv[i] = rsqrtf((float)(g_count[i] + 1));  // +1 self-loop
}

__global__ void k_scanA() {
    __shared__ int sh[SCAN_BLK];
    int i = blockIdx.x * SCAN_BLK + threadIdx.x;
    sh[threadIdx.x] = (i < NN) ? g_count[i] : 0;
    __syncthreads();
    for (int off = SCAN_BLK / 2; off > 0; off >>= 1) {
        if (threadIdx.x < off) sh[threadIdx.x] += sh[threadIdx.x + off];
        __syncthreads();
    }
    if (threadIdx.x == 0) g_bsum[blockIdx.x] = sh[0];
}

__global__ void k_scanB() {
    __shared__ int sh[NSCAN];
    if (threadIdx.x < NSCAN) sh[threadIdx.x] = g_bsum[threadIdx.x];
    __syncthreads();
    if (threadIdx.x == 0) {
        int run = 0;
        for (int b = 0; b < NSCAN; b++) { int t = sh[b]; sh[b] = run; run += t; }
        g_rowptr[NN] = run;
    }
    __syncthreads();
    if (threadIdx.x < NSCAN) g_boff[threadIdx.x] = sh[threadIdx.x];
}

__global__ void k_scanC() {
    __shared__ int sh[SCAN_BLK];
    int i = blockIdx.x * SCAN_BLK + threadIdx.x;
    int v = (i < NN) ? g_count[i] : 0;
    sh[threadIdx.x] = v;
    __syncthreads();
    for (int off = 1; off < SCAN_BLK; off <<= 1) {
        int t = (threadIdx.x >= off) ? sh[threadIdx.x - off] : 0;
        __syncthreads();
        sh[threadIdx.x] += t;
        __syncthreads();
    }
    if (i < NN) {
        int excl = sh[threadIdx.x] - v + g_boff[blockIdx.x];
        g_rowptr[i] = excl;
        g_cursor[i] = excl;
    }
}

__global__ void k_fill(const int* __restrict__ src, const int* __restrict__ dst) {
    int e = blockIdx.x * blockDim.x + threadIdx.x;
    if (e >= NE) return;
    int s = src[e], d = dst[e];
    int idx = atomicAdd(&g_cursor[d], 1);
    g_csr_src[idx] = s;
    g_csr_w[idx]   = g_dinv[s] * g_dinv[d];
}

// ---------------- 128x128 SGEMM: C[N,128] = A[N,128] @ W[128,128] ----------------
// BM=128, BN=128, BK=8, 256 threads, 8x8 microtile (split 4+4).
__global__ void __launch_bounds__(256) k_gemm128(const float* __restrict__ A,
                                                 const float* __restrict__ W,
                                                 float* __restrict__ C) {
    __shared__ float As[8][FD];   // transposed: As[k][row]
    __shared__ float Bs[8][FD];   // Bs[k][col]
    int tid = threadIdx.x;
    int rowBlock = blockIdx.x * 128;
    int tx = tid & 15;            // col group
    int ty = tid >> 4;            // row group (0..15)

    float acc[8][8];
#pragma unroll
    for (int i = 0; i < 8; i++)
#pragma unroll
        for (int j = 0; j < 8; j++) acc[i][j] = 0.f;

    int aRow = tid >> 1;
    int aK   = (tid & 1) * 4;
    int bK   = tid >> 5;
    int bCol = (tid & 31) * 4;

    for (int kk = 0; kk < FD; kk += 8) {
        int gr = rowBlock + aRow;
        float4 av = make_float4(0.f, 0.f, 0.f, 0.f);
        if (gr < NN) av = *(const float4*)(A + (size_t)gr * FD + kk + aK);
        As[aK + 0][aRow] = av.x;
        As[aK + 1][aRow] = av.y;
        As[aK + 2][aRow] = av.z;
        As[aK + 3][aRow] = av.w;
        *(float4*)&Bs[bK][bCol] = *(const float4*)(W + (size_t)(kk + bK) * FD + bCol);
        __syncthreads();
#pragma unroll
        for (int k = 0; k < 8; k++) {
            float a[8], b[8];
            *(float4*)&a[0] = *(float4*)&As[k][ty * 4];
            *(float4*)&a[4] = *(float4*)&As[k][64 + ty * 4];
            *(float4*)&b[0] = *(float4*)&Bs[k][tx * 4];
            *(float4*)&b[4] = *(float4*)&Bs[k][64 + tx * 4];
#pragma unroll
            for (int i = 0; i < 8; i++)
#pragma unroll
                for (int j = 0; j < 8; j++)
                    acc[i][j] = fmaf(a[i], b[j], acc[i][j]);
        }
        __syncthreads();
    }

#pragma unroll
    for (int i = 0; i < 8; i++) {
        int r = (i < 4) ? (ty * 4 + i) : (64 + ty * 4 + i - 4);
        int gr = rowBlock + r;
        if (gr < NN) {
            *(float4*)(C + (size_t)gr * FD + tx * 4) =
                make_float4(acc[i][0], acc[i][1], acc[i][2], acc[i][3]);
            *(float4*)(C + (size_t)gr * FD + 64 + tx * 4) =
                make_float4(acc[i][4], acc[i][5], acc[i][6], acc[i][7]);
        }
    }
}

// ---------------- aggregation + bias + LN + ReLU (warp per node) ----------------
__global__ void __launch_bounds__(256) k_agg_ln(const float* __restrict__ h,
                                                const float* __restrict__ bias,
                                                const float* __restrict__ gamma,
                                                const float* __restrict__ beta,
                                                float* __restrict__ out) {
    int gw = (blockIdx.x * blockDim.x + threadIdx.x) >> 5;
    if (gw >= NN) return;
    int lane = threadIdx.x & 31;
    int c0 = lane * 4;
    int node = gw;

    float dn = g_dinv[node];
    float sw = dn * dn;
    float4 hv = *(const float4*)(h + (size_t)node * FD + c0);
    float ax = sw * hv.x, ay = sw * hv.y, az = sw * hv.z, aw = sw * hv.w;

    int e   = g_rowptr[node];
    int end = g_rowptr[node + 1];
    for (; e + 4 <= end; e += 4) {
        int   s0 = g_csr_src[e],     s1 = g_csr_src[e + 1];
        int   s2 = g_csr_src[e + 2], s3 = g_csr_src[e + 3];
        float w0 = g_csr_w[e],       w1 = g_csr_w[e + 1];
        float w2 = g_csr_w[e + 2],   w3 = g_csr_w[e + 3];
        float4 v0 = *(const float4*)(h + (size_t)s0 * FD + c0);
        float4 v1 = *(const float4*)(h + (size_t)s1 * FD + c0);
        float4 v2 = *(const float4*)(h + (size_t)s2 * FD + c0);
        float4 v3 = *(const float4*)(h + (size_t)s3 * FD + c0);
        ax += w0 * v0.x + w1 * v1.x + w2 * v2.x + w3 * v3.x;
        ay += w0 * v0.y + w1 * v1.y + w2 * v2.y + w3 * v3.y;
        az += w0 * v0.z + w1 * v1.z + w2 * v2.z + w3 * v3.z;
        aw += w0 * v0.w + w1 * v1.w + w2 * v2.w + w3 * v3.w;
    }
    for (; e < end; e++) {
        int s = g_csr_src[e];
        float w = g_csr_w[e];
        float4 v = *(const float4*)(h + (size_t)s * FD + c0);
        ax += w * v.x; ay += w * v.y; az += w * v.z; aw += w * v.w;
    }

    float4 b4 = *(const float4*)(bias + c0);
    float xx = ax + b4.x, xy = ay + b4.y, xz = az + b4.z, xw = aw + b4.w;

    float s = xx + xy + xz + xw;
#pragma unroll
    for (int o = 16; o > 0; o >>= 1) s += __shfl_xor_sync(0xffffffffu, s, o);
    float mean = s * (1.f / FD);
    float dx = xx - mean, dy = xy - mean, dz = xz - mean, dw = xw - mean;
    float ss = dx * dx + dy * dy + dz * dz + dw * dw;
#pragma unroll
    for (int o = 16; o > 0; o >>= 1) ss += __shfl_xor_sync(0xffffffffu, ss, o);
    float inv = rsqrtf(ss * (1.f / FD) + LN_EPS);

    float4 g4  = *(const float4*)(gamma + c0);
    float4 be4 = *(const float4*)(beta + c0);
    float4 y;
    y.x = fmaxf(dx * inv * g4.x + be4.x, 0.f);
    y.y = fmaxf(dy * inv * g4.y + be4.y, 0.f);
    y.z = fmaxf(dz * inv * g4.z + be4.z, 0.f);
    y.w = fmaxf(dw * inv * g4.w + be4.w, 0.f);
    *(float4*)(out + (size_t)node * FD + c0) = y;
}

// ---------------- GEMM3: [N,128] @ [128,40] (warp per row) ----------------
__global__ void __launch_bounds__(256) k_gemm3(const float* __restrict__ A,
                                               const float* __restrict__ W3,
                                               float* __restrict__ out) {
    __shared__ float Ws[FD * NC];  // 20 KB, Ws[k*40 + c]
    int tid = threadIdx.x;
    for (int i = tid; i < FD * NC; i += blockDim.x) Ws[i] = W3[i];
    __syncthreads();

    int row = blockIdx.x * (blockDim.x >> 5) + (tid >> 5);
    if (row >= NN) return;
    int lane = tid & 31;
    const float* a = A + (size_t)row * FD;

    float acc0 = 0.f, acc1 = 0.f;
#pragma unroll
    for (int k = 0; k < FD; k++) {
        float xk = a[k];
        acc0 = fmaf(xk, Ws[k * NC + lane], acc0);
        if (lane < 8) acc1 = fmaf(xk, Ws[k * NC + 32 + lane], acc1);
    }
    out[(size_t)row * NC + lane] = acc0;
    if (lane < 8) out[(size_t)row * NC + 32 + lane] = acc1;
}

// ---------------- output aggregation + bias + log_softmax ----------------
__global__ void __launch_bounds__(256) k_agg_out(const float* __restrict__ h3,
                                                 const float* __restrict__ b3,
                                                 float* __restrict__ out) {
    int gw = (blockIdx.x * blockDim.x + threadIdx.x) >> 5;
    if (gw >= NN) return;
    int lane = threadIdx.x & 31;
    int node = gw;
    bool hi = lane < (NC - 32);  // lanes 0..7 also own col 32+lane

    float dn = g_dinv[node];
    float sw = dn * dn;
    float a0 = sw * h3[(size_t)node * NC + lane];
    float a1 = hi ? sw * h3[(size_t)node * NC + 32 + lane] : 0.f;

    int e   = g_rowptr[node];
    int end = g_rowptr[node + 1];
    for (; e < end; e++) {
        int s = g_csr_src[e];
        float w = g_csr_w[e];
        a0 = fmaf(w, h3[(size_t)s * NC + lane], a0);
        if (hi) a1 = fmaf(w, h3[(size_t)s * NC + 32 + lane], a1);
    }

    float x0 = a0 + b3[lane];
    float x1 = hi ? (a1 + b3[32 + lane]) : -1e30f;

    float m = fmaxf(x0, x1);
#pragma unroll
    for (int o = 16; o > 0; o >>= 1) m = fmaxf(m, __shfl_xor_sync(0xffffffffu, m, o));
    float se = __expf(x0 - m) + (hi ? __expf(x1 - m) : 0.f);
#pragma unroll
    for (int o = 16; o > 0; o >>= 1) se += __shfl_xor_sync(0xffffffffu, se, o);
    float L = m + __logf(se);

    out[(size_t)node * NC + lane] = x0 - L;
    if (hi) out[(size_t)node * NC + 32 + lane] = x1 - L;
}

// ---------------- launch ----------------
extern "C" void kernel_launch(void* const* d_in, const int* in_sizes, int n_in,
                              void* d_out, int out_size) {
    const float* x    = (const float*)d_in[0];
    const int*   ei   = (const int*)d_in[1];
    const float* W1   = (const float*)d_in[2];
    const float* b1   = (const float*)d_in[3];
    const float* g1   = (const float*)d_in[4];
    const float* be1  = (const float*)d_in[5];
    const float* W2   = (const float*)d_in[6];
    const float* b2   = (const float*)d_in[7];
    const float* g2   = (const float*)d_in[8];
    const float* be2  = (const float*)d_in[9];
    const float* W3   = (const float*)d_in[10];
    const float* b3   = (const float*)d_in[11];
    float* out = (float*)d_out;

    const int* src = ei;
    const int* dst = ei + NE;

    float *hA, *hB, *h3, *dummy;
    // device symbols referenced directly by kernels; grab addresses for passing
    cudaGetSymbolAddress((void**)&hA, g_hA);
    cudaGetSymbolAddress((void**)&hB, g_hB);
    cudaGetSymbolAddress((void**)&h3, g_h3);
    (void)dummy; (void)n_in; (void)in_sizes; (void)out_size;

    int tN = (NN + 255) / 256;
    int tE = (NE + 255) / 256;

    // CSR build (per replay; deterministic up to fp summation order)
    k_init_count<<<tN, 256>>>();
    k_hist<<<tE, 256>>>(dst);
    k_dinv<<<tN, 256>>>();
    k_scanA<<<NSCAN, SCAN_BLK>>>();
    k_scanB<<<1, 128>>>();
    k_scanC<<<NSCAN, SCAN_BLK>>>();
    k_fill<<<tE, 256>>>(src, dst);

    int gGemm = (NN + 127) / 128;
    int gWarp = (NN * 32 + 255) / 256;

    // layer 1
    k_gemm128<<<gGemm, 256>>>(x, W1, hA);
    k_agg_ln<<<gWarp, 256>>>(hA, b1, g1, be1, hB);
    // layer 2
    k_gemm128<<<gGemm, 256>>>(hB, W2, hA);
    k_agg_ln<<<gWarp, 256>>>(hA, b2, g2, be2, hB);
    // output layer
    k_gemm3<<<gWarp, 256>>>(hB, W3, h3);
    k_agg_out<<<gWarp, 256>>>(h3, b3, out);
}